// round 6
// baseline (speedup 1.0000x reference)
#include <cuda_runtime.h>
#include <math.h>
#include <stdint.h>

#define HIDDEN  256
#define N_PROT  12288
#define N_MOL   6144
#define N_BATCH 32
#define TQ      16                      // prot rows per attn block
#define MSEG    384                     // max mol rows per batch (mean 192, sd 13.6 -> 14 sigma)
#define SCTS    20                      // sc_t stride in floats (80B: 16B-aligned, 4-way-conflict worst)
#define CKEYS   32                      // K rows staged per chunk (32 KB smem)
#define MAXTILES (N_PROT / TQ + N_BATCH)

#define NPROJ   1536                    // proj blocks (Q:768, K:384, V:384)
#define NZERO   4608                    // zero-fill blocks for attn matrix
#define ATTN_F4 ((size_t)N_PROT * N_MOL / 4)

// Scratch (device globals: allocation-free per harness rules)
__device__ float g_Q[N_PROT * HIDDEN];
__device__ float g_K[N_MOL * HIDDEN];
__device__ float g_V[N_MOL * HIDDEN];
__device__ int   g_ms[N_BATCH + 1];
__device__ int   g_ps[N_BATCH + 1];
__device__ int   g_ss[N_BATCH];
__device__ int   g_se[N_BATCH];
__device__ int   g_trow[MAXTILES];
__device__ int   g_tn[MAXTILES];
__device__ int   g_tb[MAXTILES];
__device__ int   g_ntiles;

// ---- f32x2 helpers (FFMA2 is PTX-only; ptxas never auto-fuses) -----------
__device__ __forceinline__ unsigned long long ffma2(
    unsigned long long a, unsigned long long b, unsigned long long c)
{
    unsigned long long d;
    asm("fma.rn.f32x2 %0, %1, %2, %3;" : "=l"(d) : "l"(a), "l"(b), "l"(c));
    return d;
}
__device__ __forceinline__ unsigned long long pack2(float lo, float hi)
{
    unsigned long long p;
    asm("mov.b64 %0, {%1, %2};" : "=l"(p) : "f"(lo), "f"(hi));
    return p;
}
__device__ __forceinline__ void unpack2(unsigned long long p, float& lo, float& hi)
{
    asm("mov.b64 {%0, %1}, %2;" : "=f"(lo), "=f"(hi) : "l"(p));
}
// 128-bit shared load as two pre-paired f32x2 operands (no packing movs)
__device__ __forceinline__ void lds_v2u64(
    unsigned long long& a, unsigned long long& b, uint32_t addr)
{
    asm volatile("ld.shared.v2.u64 {%0, %1}, [%2];" : "=l"(a), "=l"(b) : "r"(addr));
}

// ---------------------------------------------------------------------------
// Parallel boundary detection on the SORTED batch arrays.
// ---------------------------------------------------------------------------
__global__ __launch_bounds__(256) void bounds_kernel(
    const int* __restrict__ prot_batch, const int* __restrict__ mol_batch)
{
    const int i = blockIdx.x * 256 + threadIdx.x;
    if (i < N_MOL) {
        const int v = mol_batch[i];
        const int p = (i > 0) ? mol_batch[i - 1] : -1;
        for (int bb = p + 1; bb <= v; bb++) g_ms[bb] = i;
        if (i == N_MOL - 1)
            for (int bb = v + 1; bb <= N_BATCH; bb++) g_ms[bb] = N_MOL;
    }
    if (i < N_PROT) {
        const int v = prot_batch[i];
        const int p = (i > 0) ? prot_batch[i - 1] : -1;
        for (int bb = p + 1; bb <= v; bb++) g_ps[bb] = i;
        if (i == N_PROT - 1)
            for (int bb = v + 1; bb <= N_BATCH; bb++) g_ps[bb] = N_PROT;
    }
}

// ---------------------------------------------------------------------------
// Tile build: 1 warp.
// ---------------------------------------------------------------------------
__global__ void tiles_kernel()
{
    const int tid = threadIdx.x;
    if (tid >= 32) return;
    g_ss[tid] = g_ms[tid];
    g_se[tid] = g_ms[tid + 1];

    const int p0 = g_ps[tid];
    const int np = g_ps[tid + 1] - p0;
    const int nt = (np + TQ - 1) / TQ;
    int off = nt;
    #pragma unroll
    for (int d = 1; d < 32; d <<= 1) {
        const int n = __shfl_up_sync(0xffffffffu, off, d);
        if (tid >= d) off += n;
    }
    const int base = off - nt;
    for (int k = 0; k < nt; k++) {
        g_trow[base + k] = p0 + k * TQ;
        g_tn[base + k]   = (np - k * TQ < TQ) ? (np - k * TQ) : TQ;
        g_tb[base + k]   = tid;
    }
    if (tid == 31) g_ntiles = off;
}

// ---------------------------------------------------------------------------
// Fused: projection GEMMs (Q,K,V) + attn-matrix zero-fill in ONE launch.
// ---------------------------------------------------------------------------
__global__ __launch_bounds__(256) void proj_zero_kernel(
    const float* __restrict__ prot_embed, const float* __restrict__ mol_embed,
    const float* __restrict__ Wq, const float* __restrict__ bq,
    const float* __restrict__ Wk, const float* __restrict__ bk,
    const float* __restrict__ Wv, const float* __restrict__ bv,
    float* __restrict__ attn)
{
    const int bid = blockIdx.x;

    if (bid & 3) {
        const size_t zidx = (size_t)(bid - (bid >> 2) - 1);
        float4* a4 = (float4*)attn;
        const float4 z = {0.f, 0.f, 0.f, 0.f};
        const size_t stride = (size_t)NZERO * 256;
        for (size_t i = zidx * 256 + threadIdx.x; i < ATTN_F4; i += stride)
            a4[i] = z;
        return;
    }

    constexpr int BM = 64, BN = 64, BK = 16;
    __shared__ __align__(16) float Xs[BK][BM + 4];
    __shared__ __align__(16) float Ws[BK][BN + 4];

    const int gb = bid >> 2;
    const float* X; const float* W; const float* bias; float* C;
    int local;
    if (gb < 768)       { local = gb;        X = prot_embed; W = Wq; bias = bq; C = g_Q; }
    else if (gb < 1152) { local = gb - 768;  X = mol_embed;  W = Wk; bias = bk; C = g_K; }
    else                { local = gb - 1152; X = mol_embed;  W = Wv; bias = bv; C = g_V; }
    const int row0 = (local >> 2) * BM;
    const int col0 = (local & 3) * BN;

    const int tx = threadIdx.x & 15;
    const int ty = threadIdx.x >> 4;
    const int lk = threadIdx.x & (BK - 1);
    const int lr = threadIdx.x / BK;

    float acc[4][4] = {};

    for (int k0 = 0; k0 < HIDDEN; k0 += BK) {
        #pragma unroll
        for (int r = 0; r < BM; r += 16) {
            Xs[lk][lr + r] = X[(size_t)(row0 + lr + r) * HIDDEN + k0 + lk];
            Ws[lk][lr + r] = W[(size_t)(col0 + lr + r) * HIDDEN + k0 + lk];
        }
        __syncthreads();
        #pragma unroll
        for (int kk = 0; kk < BK; kk++) {
            const float4 a = *(const float4*)&Xs[kk][ty * 4];
            const float4 b = *(const float4*)&Ws[kk][tx * 4];
            const float av[4] = {a.x, a.y, a.z, a.w};
            const float bv4[4] = {b.x, b.y, b.z, b.w};
            #pragma unroll
            for (int i = 0; i < 4; i++)
                #pragma unroll
                for (int j = 0; j < 4; j++)
                    acc[i][j] = fmaf(av[i], bv4[j], acc[i][j]);
        }
        __syncthreads();
    }

    #pragma unroll
    for (int i = 0; i < 4; i++) {
        #pragma unroll
        for (int j = 0; j < 4; j++) {
            const int c = col0 + tx * 4 + j;
            C[(size_t)(row0 + ty * 4 + i) * HIDDEN + c] = acc[i][j] + bias[c];
        }
    }
}

// ---------------------------------------------------------------------------
// Attention: one block (256 threads) per tile of TQ=16 prot rows.
// Score phase: 4 rows/warp via 8-lane quarters, keys split across warp halves,
//   f32x2 FMAs with operands loaded pre-paired (ld.shared.v2.u64).
// Scores stored TRANSPOSED: sc_t[key*SCTS + row].
// PV phase: per key, 4 broadcast ld.shared.v2.u64 give 8 row-pair f32x2;
//   accumulators are row-pairs; only ONE pack (v,v) per key.
// ---------------------------------------------------------------------------
__global__ __launch_bounds__(256, 3) void attn_kernel(
    float* __restrict__ out, float* __restrict__ attn)
{
    const int t = blockIdx.x;
    if (t >= g_ntiles) return;

    const int row0 = g_trow[t];
    const int nr   = g_tn[t];
    const int b    = g_tb[t];
    const int s    = g_ss[b];
    int m = g_se[b] - s;
    if (m > MSEG) m = MSEG;          // unreachable; memory safety
    const int e_eff = s + m;

    __shared__ __align__(16) float sc_t[MSEG * SCTS];    // 30 KB, [key][row]
    __shared__ __align__(16) float Ks[CKEYS * HIDDEN];   // 32 KB

    const int tid  = threadIdx.x;
    const int warp = tid >> 5;
    const int lane = tid & 31;

    const uint32_t ks_base  = (uint32_t)__cvta_generic_to_shared(Ks);
    const uint32_t sct_base = (uint32_t)__cvta_generic_to_shared(sc_t);

    if (m > 0) {
        // ---- score phase ----
        const int q   = lane >> 3;           // quarter 0..3 -> row within group
        const int ql  = lane & 7;            // lane within quarter
        const int row = (warp & 3) * 4 + q;  // 0..15, unique per (warp&3, q)
        const int kh  = warp >> 2;           // key-half
        const int qr  = row0 + ((row < nr) ? row : nr - 1);

        // Q dims [ql*32, ql*32+32) as 16 pre-paired f32x2
        unsigned long long qp[16];
        {
            const float4* Qg = (const float4*)g_Q + (size_t)qr * 64 + ql * 8;
            #pragma unroll
            for (int i = 0; i < 8; i++) {
                const float4 f = Qg[i];
                qp[2 * i]     = pack2(f.x, f.y);
                qp[2 * i + 1] = pack2(f.z, f.w);
            }
        }

        float4* Ks4 = (float4*)Ks;
        for (int c0 = 0; c0 < m; c0 += CKEYS) {
            const int cn = (m - c0 < CKEYS) ? (m - c0) : CKEYS;
            __syncthreads();
            const float4* Kg = (const float4*)g_K + (size_t)(s + c0) * 64;
            for (int idx = tid; idx < cn * 64; idx += 256)
                Ks4[idx] = Kg[idx];
            __syncthreads();

            const int jlo = kh ? (cn >> 1) : 0;
            const int jhi = kh ? cn : (cn >> 1);
            for (int j = jlo; j < jhi; j++) {
                const uint32_t kb = ks_base + (uint32_t)j * 1024u + (uint32_t)ql * 128u;
                unsigned long long a0 = 0ull, a1 = 0ull;
                #pragma unroll
                for (int i = 0; i < 8; i++) {
                    unsigned long long ka, kb2;
                    lds_v2u64(ka, kb2, kb + i * 16);
                    a0 = ffma2(qp[2 * i], ka, a0);
                    a1 = ffma2(qp[2 * i + 1], kb2, a1);
                }
                float l0, h0, l1, h1;
                unpack2(a0, l0, h0);
                unpack2(a1, l1, h1);
                float d = (l0 + h0) + (l1 + h1);
                d += __shfl_xor_sync(0xffffffffu, d, 4);
                d += __shfl_xor_sync(0xffffffffu, d, 2);
                d += __shfl_xor_sync(0xffffffffu, d, 1);
                if (ql == 0) sc_t[(c0 + j) * SCTS + row] = d * 0.0625f;  // 1/sqrt(256)
            }
        }
        __syncthreads();

        // ---- softmax: warp w normalizes rows 2w, 2w+1 (transposed layout) ----
        #pragma unroll
        for (int rr2 = 0; rr2 < 2; rr2++) {
            const int r = warp * 2 + rr2;
            float mx = -INFINITY;
            for (int j = lane; j < m; j += 32) mx = fmaxf(mx, sc_t[j * SCTS + r]);
            #pragma unroll
            for (int off = 16; off; off >>= 1)
                mx = fmaxf(mx, __shfl_xor_sync(0xffffffffu, mx, off));
            float sum = 0.f;
            for (int j = lane; j < m; j += 32) {
                const float v = __expf(sc_t[j * SCTS + r] - mx);
                sc_t[j * SCTS + r] = v;
                sum += v;
            }
            #pragma unroll
            for (int off = 16; off; off >>= 1)
                sum += __shfl_xor_sync(0xffffffffu, sum, off);
            const float inv = 1.f / sum;
            for (int j = lane; j < m; j += 32) sc_t[j * SCTS + r] *= inv;
        }
        __syncthreads();
    }

    // ---- segment-only attn write (matrix pre-zeroed) ----
    for (int r = 0; r < nr; r++) {
        float* arow = attn + (size_t)(row0 + r) * N_MOL;
        for (int c = s + tid; c < e_eff; c += 256)
            arow[c] = sc_t[(c - s) * SCTS + r];
    }

    // ---- PV: acc2[k] = f32x2 over rows (2k, 2k+1), channel = tid ----
    unsigned long long acc2[8];
    #pragma unroll
    for (int k = 0; k < 8; k++) acc2[k] = 0ull;

    for (int j = 0; j < m; j++) {
        const uint32_t pb = sct_base + (uint32_t)j * (SCTS * 4u);
        unsigned long long p01, p23, p45, p67, p89, pab, pcd, pef;
        lds_v2u64(p01, p23, pb);         // rows 0-3
        lds_v2u64(p45, p67, pb + 16);    // rows 4-7
        lds_v2u64(p89, pab, pb + 32);    // rows 8-11
        lds_v2u64(pcd, pef, pb + 48);    // rows 12-15
        const float v = g_V[(size_t)(s + j) * HIDDEN + tid];
        const unsigned long long vv = pack2(v, v);
        acc2[0] = ffma2(p01, vv, acc2[0]);
        acc2[1] = ffma2(p23, vv, acc2[1]);
        acc2[2] = ffma2(p45, vv, acc2[2]);
        acc2[3] = ffma2(p67, vv, acc2[3]);
        acc2[4] = ffma2(p89, vv, acc2[4]);
        acc2[5] = ffma2(pab, vv, acc2[5]);
        acc2[6] = ffma2(pcd, vv, acc2[6]);
        acc2[7] = ffma2(pef, vv, acc2[7]);
    }

    #pragma unroll
    for (int k = 0; k < 8; k++) {
        float lo, hi;
        unpack2(acc2[k], lo, hi);
        const int r = 2 * k;
        if (r     < nr) out[(size_t)(row0 + r    ) * HIDDEN + tid] = lo;
        if (r + 1 < nr) out[(size_t)(row0 + r + 1) * HIDDEN + tid] = hi;
    }
}

// ---------------------------------------------------------------------------
extern "C" void kernel_launch(void* const* d_in, const int* in_sizes, int n_in,
                              void* d_out, int out_size)
{
    const float* prot_embed = (const float*)d_in[0];
    const float* mol_embed  = (const float*)d_in[1];
    const int*   prot_batch = (const int*)d_in[2];
    const int*   mol_batch  = (const int*)d_in[3];
    const float* Wq = (const float*)d_in[4];
    const float* bq = (const float*)d_in[5];
    const float* Wk = (const float*)d_in[6];
    const float* bk = (const float*)d_in[7];
    const float* Wv = (const float*)d_in[8];
    const float* bv = (const float*)d_in[9];

    float* out  = (float*)d_out;                              // [N_PROT, HIDDEN]
    float* attn = (float*)d_out + (size_t)N_PROT * HIDDEN;    // [N_PROT, N_MOL]

    bounds_kernel<<<(N_PROT + 255) / 256, 256>>>(prot_batch, mol_batch);
    tiles_kernel<<<1, 32>>>();
    proj_zero_kernel<<<NPROJ + NZERO, 256>>>(prot_embed, mol_embed,
                                             Wq, bq, Wk, bk, Wv, bv, attn);
    attn_kernel<<<MAXTILES, 256>>>(out, attn);
}

// round 7
// speedup vs baseline: 2.4472x; 2.4472x over previous
#include <cuda_runtime.h>
#include <math.h>
#include <stdint.h>

#define HIDDEN  256
#define N_PROT  12288
#define N_MOL   6144
#define N_BATCH 32
#define TQ      16                      // prot rows per attn block
#define MSEG    512                     // max mol rows per batch (mean 192; huge margin)
#define CKEYS   32                      // K rows staged per chunk (32 KB smem)
#define MAXTILES (N_PROT / TQ + N_BATCH)

#define NPROJ   1536                    // proj blocks (Q:768, K:384, V:384)
#define NZERO   4608                    // zero-fill blocks for attn matrix
#define ATTN_F4 ((size_t)N_PROT * N_MOL / 4)

// Scratch (device globals: allocation-free per harness rules)
__device__ float g_Q[N_PROT * HIDDEN];
__device__ float g_K[N_MOL * HIDDEN];
__device__ float g_V[N_MOL * HIDDEN];
__device__ int   g_ms[N_BATCH + 1];
__device__ int   g_ps[N_BATCH + 1];
__device__ int   g_ss[N_BATCH];
__device__ int   g_se[N_BATCH];
__device__ int   g_trow[MAXTILES];
__device__ int   g_tn[MAXTILES];
__device__ int   g_tb[MAXTILES];
__device__ int   g_ntiles;

// ---- f32x2 helpers (FFMA2 is PTX-only; ptxas never auto-fuses) -----------
__device__ __forceinline__ unsigned long long ffma2(
    unsigned long long a, unsigned long long b, unsigned long long c)
{
    unsigned long long d;
    asm("fma.rn.f32x2 %0, %1, %2, %3;" : "=l"(d) : "l"(a), "l"(b), "l"(c));
    return d;
}
__device__ __forceinline__ unsigned long long pack2(float lo, float hi)
{
    unsigned long long p;
    asm("mov.b64 %0, {%1, %2};" : "=l"(p) : "f"(lo), "f"(hi));
    return p;
}
__device__ __forceinline__ void unpack2(unsigned long long p, float& lo, float& hi)
{
    asm("mov.b64 {%0, %1}, %2;" : "=f"(lo), "=f"(hi) : "l"(p));
}
// 128-bit shared load as two pre-paired f32x2 operands (ONE LDS.128)
__device__ __forceinline__ void lds_v2u64(
    unsigned long long& a, unsigned long long& b, uint32_t addr)
{
    asm volatile("ld.shared.v2.u64 {%0, %1}, [%2];" : "=l"(a), "=l"(b) : "r"(addr));
}

// ---------------------------------------------------------------------------
// Parallel boundary detection on the SORTED batch arrays.
// ---------------------------------------------------------------------------
__global__ __launch_bounds__(256) void bounds_kernel(
    const int* __restrict__ prot_batch, const int* __restrict__ mol_batch)
{
    const int i = blockIdx.x * 256 + threadIdx.x;
    if (i < N_MOL) {
        const int v = mol_batch[i];
        const int p = (i > 0) ? mol_batch[i - 1] : -1;
        for (int bb = p + 1; bb <= v; bb++) g_ms[bb] = i;
        if (i == N_MOL - 1)
            for (int bb = v + 1; bb <= N_BATCH; bb++) g_ms[bb] = N_MOL;
    }
    if (i < N_PROT) {
        const int v = prot_batch[i];
        const int p = (i > 0) ? prot_batch[i - 1] : -1;
        for (int bb = p + 1; bb <= v; bb++) g_ps[bb] = i;
        if (i == N_PROT - 1)
            for (int bb = v + 1; bb <= N_BATCH; bb++) g_ps[bb] = N_PROT;
    }
}

// ---------------------------------------------------------------------------
// Tile build: 1 warp.
// ---------------------------------------------------------------------------
__global__ void tiles_kernel()
{
    const int tid = threadIdx.x;
    if (tid >= 32) return;
    g_ss[tid] = g_ms[tid];
    g_se[tid] = g_ms[tid + 1];

    const int p0 = g_ps[tid];
    const int np = g_ps[tid + 1] - p0;
    const int nt = (np + TQ - 1) / TQ;
    int off = nt;
    #pragma unroll
    for (int d = 1; d < 32; d <<= 1) {
        const int n = __shfl_up_sync(0xffffffffu, off, d);
        if (tid >= d) off += n;
    }
    const int base = off - nt;
    for (int k = 0; k < nt; k++) {
        g_trow[base + k] = p0 + k * TQ;
        g_tn[base + k]   = (np - k * TQ < TQ) ? (np - k * TQ) : TQ;
        g_tb[base + k]   = tid;
    }
    if (tid == 31) g_ntiles = off;
}

// ---------------------------------------------------------------------------
// Fused: projection GEMMs (Q,K,V) + attn-matrix zero-fill in ONE launch.
// ---------------------------------------------------------------------------
__global__ __launch_bounds__(256) void proj_zero_kernel(
    const float* __restrict__ prot_embed, const float* __restrict__ mol_embed,
    const float* __restrict__ Wq, const float* __restrict__ bq,
    const float* __restrict__ Wk, const float* __restrict__ bk,
    const float* __restrict__ Wv, const float* __restrict__ bv,
    float* __restrict__ attn)
{
    const int bid = blockIdx.x;

    if (bid & 3) {
        const size_t zidx = (size_t)(bid - (bid >> 2) - 1);
        float4* a4 = (float4*)attn;
        const float4 z = {0.f, 0.f, 0.f, 0.f};
        const size_t stride = (size_t)NZERO * 256;
        for (size_t i = zidx * 256 + threadIdx.x; i < ATTN_F4; i += stride)
            a4[i] = z;
        return;
    }

    constexpr int BM = 64, BN = 64, BK = 16;
    __shared__ __align__(16) float Xs[BK][BM + 4];
    __shared__ __align__(16) float Ws[BK][BN + 4];

    const int gb = bid >> 2;
    const float* X; const float* W; const float* bias; float* C;
    int local;
    if (gb < 768)       { local = gb;        X = prot_embed; W = Wq; bias = bq; C = g_Q; }
    else if (gb < 1152) { local = gb - 768;  X = mol_embed;  W = Wk; bias = bk; C = g_K; }
    else                { local = gb - 1152; X = mol_embed;  W = Wv; bias = bv; C = g_V; }
    const int row0 = (local >> 2) * BM;
    const int col0 = (local & 3) * BN;

    const int tx = threadIdx.x & 15;
    const int ty = threadIdx.x >> 4;
    const int lk = threadIdx.x & (BK - 1);
    const int lr = threadIdx.x / BK;

    float acc[4][4] = {};

    for (int k0 = 0; k0 < HIDDEN; k0 += BK) {
        #pragma unroll
        for (int r = 0; r < BM; r += 16) {
            Xs[lk][lr + r] = X[(size_t)(row0 + lr + r) * HIDDEN + k0 + lk];
            Ws[lk][lr + r] = W[(size_t)(col0 + lr + r) * HIDDEN + k0 + lk];
        }
        __syncthreads();
        #pragma unroll
        for (int kk = 0; kk < BK; kk++) {
            const float4 a = *(const float4*)&Xs[kk][ty * 4];
            const float4 b = *(const float4*)&Ws[kk][tx * 4];
            const float av[4] = {a.x, a.y, a.z, a.w};
            const float bv4[4] = {b.x, b.y, b.z, b.w};
            #pragma unroll
            for (int i = 0; i < 4; i++)
                #pragma unroll
                for (int j = 0; j < 4; j++)
                    acc[i][j] = fmaf(av[i], bv4[j], acc[i][j]);
        }
        __syncthreads();
    }

    #pragma unroll
    for (int i = 0; i < 4; i++) {
        #pragma unroll
        for (int j = 0; j < 4; j++) {
            const int c = col0 + tx * 4 + j;
            C[(size_t)(row0 + ty * 4 + i) * HIDDEN + c] = acc[i][j] + bias[c];
        }
    }
}

// ---------------------------------------------------------------------------
// Attention (R5 structure, f32x2 on unchanged conflict-free addresses):
// one block (256 threads) per tile of TQ=16 prot rows (same batch).
// Score: half-warp per row (hl = lane&15, 16B-stride loads = conflict-free),
//   K loaded as ld.shared.v2.u64 -> 8 FFMA2 per key.
// sc ROW-MAJOR [row*MSEG + key] (unchanged from R5).
// PV: pair over KEYS: sc[r*MSEG + j..j+3] contiguous -> one broadcast
//   ld.shared.v2.u64 per row per 4 keys; acc2[r] lo/hi = even/odd key partials.
// ---------------------------------------------------------------------------
__global__ __launch_bounds__(256) void attn_kernel(
    float* __restrict__ out, float* __restrict__ attn)
{
    const int t = blockIdx.x;
    if (t >= g_ntiles) return;

    const int row0 = g_trow[t];
    const int nr   = g_tn[t];
    const int b    = g_tb[t];
    const int s    = g_ss[b];
    int m = g_se[b] - s;
    if (m > MSEG) m = MSEG;          // unreachable; memory safety
    const int e_eff = s + m;

    __shared__ __align__(16) float sc[TQ * MSEG];        // 32 KB, [row][key]
    __shared__ __align__(16) float Ks[CKEYS * HIDDEN];   // 32 KB

    const int tid  = threadIdx.x;
    const int warp = tid >> 5;
    const int lane = tid & 31;

    const uint32_t ks_base = (uint32_t)__cvta_generic_to_shared(Ks);
    const uint32_t sc_base = (uint32_t)__cvta_generic_to_shared(sc);

    if (m > 0) {
        // Half-warp h handles row warp*2+h; hl = lane within half (0..15).
        const int h  = lane >> 4;
        const int hl = lane & 15;
        const int rr = warp * 2 + h;
        const int qr = row0 + ((rr < nr) ? rr : nr - 1);

        // Q dims for this lane (16 floats) pre-paired as 8 f32x2.
        unsigned long long qp[8];
        {
            const float4* Qg = (const float4*)g_Q + (size_t)qr * 64;
            const float4 f0 = Qg[hl];
            const float4 f1 = Qg[hl + 16];
            const float4 f2 = Qg[hl + 32];
            const float4 f3 = Qg[hl + 48];
            qp[0] = pack2(f0.x, f0.y); qp[1] = pack2(f0.z, f0.w);
            qp[2] = pack2(f1.x, f1.y); qp[3] = pack2(f1.z, f1.w);
            qp[4] = pack2(f2.x, f2.y); qp[5] = pack2(f2.z, f2.w);
            qp[6] = pack2(f3.x, f3.y); qp[7] = pack2(f3.z, f3.w);
        }

        float4* Ks4 = (float4*)Ks;
        for (int c0 = 0; c0 < m; c0 += CKEYS) {
            const int cn = (m - c0 < CKEYS) ? (m - c0) : CKEYS;
            __syncthreads();
            const float4* Kg = (const float4*)g_K + (size_t)(s + c0) * 64;
            for (int idx = tid; idx < cn * 64; idx += 256)
                Ks4[idx] = Kg[idx];
            __syncthreads();

            for (int j = 0; j < cn; j++) {
                // Same addresses as R5: Ks + j*256 floats + {hl, hl+16, hl+32, hl+48} float4s
                const uint32_t kb = ks_base + (uint32_t)j * 1024u + (uint32_t)hl * 16u;
                unsigned long long k0, k1, k2, k3, k4, k5, k6, k7;
                lds_v2u64(k0, k1, kb);
                lds_v2u64(k2, k3, kb + 256u);
                lds_v2u64(k4, k5, kb + 512u);
                lds_v2u64(k6, k7, kb + 768u);
                unsigned long long a0 = ffma2(qp[0], k0, 0ull);
                unsigned long long a1 = ffma2(qp[1], k1, 0ull);
                a0 = ffma2(qp[2], k2, a0);
                a1 = ffma2(qp[3], k3, a1);
                a0 = ffma2(qp[4], k4, a0);
                a1 = ffma2(qp[5], k5, a1);
                a0 = ffma2(qp[6], k6, a0);
                a1 = ffma2(qp[7], k7, a1);
                float l0, h0, l1, h1;
                unpack2(a0, l0, h0);
                unpack2(a1, l1, h1);
                float d = (l0 + h0) + (l1 + h1);
                #pragma unroll
                for (int off = 8; off; off >>= 1)
                    d += __shfl_xor_sync(0xffffffffu, d, off);
                if (hl == 0) sc[rr * MSEG + c0 + j] = d * 0.0625f;  // 1/sqrt(256)
            }
        }
        __syncthreads();

        // Softmax: warp w normalizes rows 2w, 2w+1 (row-major, as in R5).
        #pragma unroll
        for (int rr2 = 0; rr2 < 2; rr2++) {
            float* row = sc + (warp * 2 + rr2) * MSEG;
            float mx = -INFINITY;
            for (int j = lane; j < m; j += 32) mx = fmaxf(mx, row[j]);
            #pragma unroll
            for (int off = 16; off; off >>= 1)
                mx = fmaxf(mx, __shfl_xor_sync(0xffffffffu, mx, off));
            float sum = 0.f;
            for (int j = lane; j < m; j += 32) {
                const float v = __expf(row[j] - mx);
                row[j] = v;
                sum += v;
            }
            #pragma unroll
            for (int off = 16; off; off >>= 1)
                sum += __shfl_xor_sync(0xffffffffu, sum, off);
            const float inv = 1.f / sum;
            for (int j = lane; j < m; j += 32) row[j] *= inv;
        }
        __syncthreads();
    }

    // Segment-only attn write (matrix pre-zeroed by proj_zero_kernel).
    for (int r = 0; r < nr; r++) {
        float* arow = attn + (size_t)(row0 + r) * N_MOL;
        const float* row = sc + r * MSEG;
        for (int c = s + tid; c < e_eff; c += 256)
            arow[c] = row[c - s];
    }

    // ---- PV: acc2[r] f32x2, lo = even-key partial, hi = odd-key partial ----
    unsigned long long acc2[TQ];
    #pragma unroll
    for (int r = 0; r < TQ; r++) acc2[r] = 0ull;

    int j = 0;
    for (; j + 3 < m; j += 4) {
        const float v0 = g_V[(size_t)(s + j + 0) * HIDDEN + tid];
        const float v1 = g_V[(size_t)(s + j + 1) * HIDDEN + tid];
        const float v2 = g_V[(size_t)(s + j + 2) * HIDDEN + tid];
        const float v3 = g_V[(size_t)(s + j + 3) * HIDDEN + tid];
        const unsigned long long vv01 = pack2(v0, v1);
        const unsigned long long vv23 = pack2(v2, v3);
        #pragma unroll
        for (int r = 0; r < TQ; r++) {
            // broadcast LDS.128: p[j], p[j+1], p[j+2], p[j+3] for row r
            unsigned long long p01, p23;
            lds_v2u64(p01, p23, sc_base + (uint32_t)(r * MSEG + j) * 4u);
            unsigned long long a = acc2[r];
            a = ffma2(p01, vv01, a);
            a = ffma2(p23, vv23, a);
            acc2[r] = a;
        }
    }
    // remainder (scalar, folded into lo half via (p, 0))
    for (; j < m; j++) {
        const float v0 = g_V[(size_t)(s + j) * HIDDEN + tid];
        const unsigned long long vv = pack2(v0, 0.f);
        #pragma unroll
        for (int r = 0; r < TQ; r++) {
            const unsigned long long pp = pack2(sc[r * MSEG + j], 0.f);
            acc2[r] = ffma2(pp, vv, acc2[r]);
        }
    }

    #pragma unroll
    for (int r = 0; r < TQ; r++) {
        float lo, hi;
        unpack2(acc2[r], lo, hi);
        if (r < nr) out[(size_t)(row0 + r) * HIDDEN + tid] = lo + hi;
    }
}

// ---------------------------------------------------------------------------
extern "C" void kernel_launch(void* const* d_in, const int* in_sizes, int n_in,
                              void* d_out, int out_size)
{
    const float* prot_embed = (const float*)d_in[0];
    const float* mol_embed  = (const float*)d_in[1];
    const int*   prot_batch = (const int*)d_in[2];
    const int*   mol_batch  = (const int*)d_in[3];
    const float* Wq = (const float*)d_in[4];
    const float* bq = (const float*)d_in[5];
    const float* Wk = (const float*)d_in[6];
    const float* bk = (const float*)d_in[7];
    const float* Wv = (const float*)d_in[8];
    const float* bv = (const float*)d_in[9];

    float* out  = (float*)d_out;                              // [N_PROT, HIDDEN]
    float* attn = (float*)d_out + (size_t)N_PROT * HIDDEN;    // [N_PROT, N_MOL]

    bounds_kernel<<<(N_PROT + 255) / 256, 256>>>(prot_batch, mol_batch);
    tiles_kernel<<<1, 32>>>();
    proj_zero_kernel<<<NPROJ + NZERO, 256>>>(prot_embed, mol_embed,
                                             Wq, bq, Wk, bk, Wv, bv, attn);
    attn_kernel<<<MAXTILES, 256>>>(out, attn);
}

// round 8
// speedup vs baseline: 2.6998x; 1.1032x over previous
#include <cuda_runtime.h>
#include <math.h>
#include <stdint.h>

#define HIDDEN  256
#define N_PROT  12288
#define N_MOL   6144
#define N_BATCH 32
#define TQ      16                      // prot rows per attn block
#define MSEG    512                     // max mol rows per batch (mean 192; huge margin)
#define CKEYS   32                      // K rows staged per chunk (32 KB smem)
#define MAXTILES (N_PROT / TQ + N_BATCH)
#define NPROJ   1536                    // proj blocks (Q:768, K:384, V:384)

// Scratch (device globals: allocation-free per harness rules)
__device__ float g_Q[N_PROT * HIDDEN];
__device__ float g_K[N_MOL * HIDDEN];
__device__ float g_V[N_MOL * HIDDEN];
__device__ int   g_ms[N_BATCH + 1];
__device__ int   g_ps[N_BATCH + 1];
__device__ int   g_ss[N_BATCH];
__device__ int   g_se[N_BATCH];
__device__ int   g_trow[MAXTILES];
__device__ int   g_tn[MAXTILES];
__device__ int   g_tb[MAXTILES];
__device__ int   g_ntiles;

// ---- f32x2 helpers (FFMA2 is PTX-only; ptxas never auto-fuses) -----------
__device__ __forceinline__ unsigned long long ffma2(
    unsigned long long a, unsigned long long b, unsigned long long c)
{
    unsigned long long d;
    asm("fma.rn.f32x2 %0, %1, %2, %3;" : "=l"(d) : "l"(a), "l"(b), "l"(c));
    return d;
}
__device__ __forceinline__ unsigned long long pack2(float lo, float hi)
{
    unsigned long long p;
    asm("mov.b64 %0, {%1, %2};" : "=l"(p) : "f"(lo), "f"(hi));
    return p;
}
__device__ __forceinline__ void unpack2(unsigned long long p, float& lo, float& hi)
{
    asm("mov.b64 {%0, %1}, %2;" : "=f"(lo), "=f"(hi) : "l"(p));
}
// 128-bit shared load as two pre-paired f32x2 operands (ONE LDS.128)
__device__ __forceinline__ void lds_v2u64(
    unsigned long long& a, unsigned long long& b, uint32_t addr)
{
    asm volatile("ld.shared.v2.u64 {%0, %1}, [%2];" : "=l"(a), "=l"(b) : "r"(addr));
}

// ---------------------------------------------------------------------------
// Parallel boundary detection on the SORTED batch arrays.
// ---------------------------------------------------------------------------
__global__ __launch_bounds__(256) void bounds_kernel(
    const int* __restrict__ prot_batch, const int* __restrict__ mol_batch)
{
    const int i = blockIdx.x * 256 + threadIdx.x;
    if (i < N_MOL) {
        const int v = mol_batch[i];
        const int p = (i > 0) ? mol_batch[i - 1] : -1;
        for (int bb = p + 1; bb <= v; bb++) g_ms[bb] = i;
        if (i == N_MOL - 1)
            for (int bb = v + 1; bb <= N_BATCH; bb++) g_ms[bb] = N_MOL;
    }
    if (i < N_PROT) {
        const int v = prot_batch[i];
        const int p = (i > 0) ? prot_batch[i - 1] : -1;
        for (int bb = p + 1; bb <= v; bb++) g_ps[bb] = i;
        if (i == N_PROT - 1)
            for (int bb = v + 1; bb <= N_BATCH; bb++) g_ps[bb] = N_PROT;
    }
}

// ---------------------------------------------------------------------------
// Tile build: 1 warp.
// ---------------------------------------------------------------------------
__global__ void tiles_kernel()
{
    const int tid = threadIdx.x;
    if (tid >= 32) return;
    g_ss[tid] = g_ms[tid];
    g_se[tid] = g_ms[tid + 1];

    const int p0 = g_ps[tid];
    const int np = g_ps[tid + 1] - p0;
    const int nt = (np + TQ - 1) / TQ;
    int off = nt;
    #pragma unroll
    for (int d = 1; d < 32; d <<= 1) {
        const int n = __shfl_up_sync(0xffffffffu, off, d);
        if (tid >= d) off += n;
    }
    const int base = off - nt;
    for (int k = 0; k < nt; k++) {
        g_trow[base + k] = p0 + k * TQ;
        g_tn[base + k]   = (np - k * TQ < TQ) ? (np - k * TQ) : TQ;
        g_tb[base + k]   = tid;
    }
    if (tid == 31) g_ntiles = off;
}

// ---------------------------------------------------------------------------
// Fused projection GEMMs (Q, K, V in ONE launch):
// C[M,256] = X[M,256] @ W[256,256]^T + bias (64x64 tile, BK=16).
// ---------------------------------------------------------------------------
__global__ __launch_bounds__(256) void proj_kernel(
    const float* __restrict__ prot_embed, const float* __restrict__ mol_embed,
    const float* __restrict__ Wq, const float* __restrict__ bq,
    const float* __restrict__ Wk, const float* __restrict__ bk,
    const float* __restrict__ Wv, const float* __restrict__ bv)
{
    constexpr int BM = 64, BN = 64, BK = 16;
    __shared__ __align__(16) float Xs[BK][BM + 4];
    __shared__ __align__(16) float Ws[BK][BN + 4];

    const int gb = blockIdx.x;
    const float* X; const float* W; const float* bias; float* C;
    int local;
    if (gb < 768)       { local = gb;        X = prot_embed; W = Wq; bias = bq; C = g_Q; }
    else if (gb < 1152) { local = gb - 768;  X = mol_embed;  W = Wk; bias = bk; C = g_K; }
    else                { local = gb - 1152; X = mol_embed;  W = Wv; bias = bv; C = g_V; }
    const int row0 = (local >> 2) * BM;
    const int col0 = (local & 3) * BN;

    const int tx = threadIdx.x & 15;
    const int ty = threadIdx.x >> 4;
    const int lk = threadIdx.x & (BK - 1);
    const int lr = threadIdx.x / BK;

    float acc[4][4] = {};

    for (int k0 = 0; k0 < HIDDEN; k0 += BK) {
        #pragma unroll
        for (int r = 0; r < BM; r += 16) {
            Xs[lk][lr + r] = X[(size_t)(row0 + lr + r) * HIDDEN + k0 + lk];
            Ws[lk][lr + r] = W[(size_t)(col0 + lr + r) * HIDDEN + k0 + lk];
        }
        __syncthreads();
        #pragma unroll
        for (int kk = 0; kk < BK; kk++) {
            const float4 a = *(const float4*)&Xs[kk][ty * 4];
            const float4 b = *(const float4*)&Ws[kk][tx * 4];
            const float av[4] = {a.x, a.y, a.z, a.w};
            const float bv4[4] = {b.x, b.y, b.z, b.w};
            #pragma unroll
            for (int i = 0; i < 4; i++)
                #pragma unroll
                for (int j = 0; j < 4; j++)
                    acc[i][j] = fmaf(av[i], bv4[j], acc[i][j]);
        }
        __syncthreads();
    }

    #pragma unroll
    for (int i = 0; i < 4; i++) {
        #pragma unroll
        for (int j = 0; j < 4; j++) {
            const int c = col0 + tx * 4 + j;
            C[(size_t)(row0 + ty * 4 + i) * HIDDEN + c] = acc[i][j] + bias[c];
        }
    }
}

// ---------------------------------------------------------------------------
// Attention: one block (256 threads) per tile of TQ=16 prot rows (same batch).
// Score: warp w covers 4 rows (group g=w&3) for HALF the keys (kh=w>>2).
//   Each half-warp computes 2 rows per key from ONE K load -> K smem bytes
//   amortized over 4 rows/warp (2x less LDS than R7). Addresses unchanged
//   (hl*16B, conflict-free).
// sc ROW-MAJOR [row*MSEG + key].
// PV: pair over KEYS (contiguous sc) with f32x2; acc lo/hi = even/odd keys.
// ---------------------------------------------------------------------------
__global__ __launch_bounds__(256) void attn_kernel(
    float* __restrict__ out, float* __restrict__ attn)
{
    const int t = blockIdx.x;
    if (t >= g_ntiles) return;

    const int row0 = g_trow[t];
    const int nr   = g_tn[t];
    const int b    = g_tb[t];
    const int s    = g_ss[b];
    int m = g_se[b] - s;
    if (m > MSEG) m = MSEG;          // unreachable; memory safety
    const int e_eff = s + m;

    __shared__ __align__(16) float sc[TQ * MSEG];        // 32 KB, [row][key]
    __shared__ __align__(16) float Ks[CKEYS * HIDDEN];   // 32 KB

    const int tid  = threadIdx.x;
    const int warp = tid >> 5;
    const int lane = tid & 31;

    const uint32_t ks_base = (uint32_t)__cvta_generic_to_shared(Ks);
    const uint32_t sc_base = (uint32_t)__cvta_generic_to_shared(sc);

    if (m > 0) {
        // warp -> (row group g, key half kh); half-warp -> 2 rows.
        const int g  = warp & 3;
        const int kh = warp >> 2;
        const int h  = lane >> 4;
        const int hl = lane & 15;
        const int rA = g * 4 + h * 2;
        const int rB = rA + 1;
        const int qrA = row0 + ((rA < nr) ? rA : nr - 1);
        const int qrB = row0 + ((rB < nr) ? rB : nr - 1);

        // Q dims for this lane (16 floats per row), pre-paired as 8 f32x2 each.
        unsigned long long qpA[8], qpB[8];
        {
            const float4* QA = (const float4*)g_Q + (size_t)qrA * 64;
            const float4* QB = (const float4*)g_Q + (size_t)qrB * 64;
            #pragma unroll
            for (int i = 0; i < 4; i++) {
                const float4 fa = QA[hl + 16 * i];
                const float4 fb = QB[hl + 16 * i];
                qpA[2 * i]     = pack2(fa.x, fa.y);
                qpA[2 * i + 1] = pack2(fa.z, fa.w);
                qpB[2 * i]     = pack2(fb.x, fb.y);
                qpB[2 * i + 1] = pack2(fb.z, fb.w);
            }
        }

        float4* Ks4 = (float4*)Ks;
        for (int c0 = 0; c0 < m; c0 += CKEYS) {
            const int cn = (m - c0 < CKEYS) ? (m - c0) : CKEYS;
            __syncthreads();
            const float4* Kg = (const float4*)g_K + (size_t)(s + c0) * 64;
            for (int idx = tid; idx < cn * 64; idx += 256)
                Ks4[idx] = Kg[idx];
            __syncthreads();

            const int jlo = kh ? (cn >> 1) : 0;
            const int jhi = kh ? cn : (cn >> 1);
            for (int j = jlo; j < jhi; j++) {
                const uint32_t kb = ks_base + (uint32_t)j * 1024u + (uint32_t)hl * 16u;
                unsigned long long k0, k1, k2, k3, k4, k5, k6, k7;
                lds_v2u64(k0, k1, kb);
                lds_v2u64(k2, k3, kb + 256u);
                lds_v2u64(k4, k5, kb + 512u);
                lds_v2u64(k6, k7, kb + 768u);
                unsigned long long a0 = ffma2(qpA[0], k0, 0ull);
                unsigned long long a1 = ffma2(qpA[1], k1, 0ull);
                unsigned long long b0 = ffma2(qpB[0], k0, 0ull);
                unsigned long long b1 = ffma2(qpB[1], k1, 0ull);
                a0 = ffma2(qpA[2], k2, a0);  b0 = ffma2(qpB[2], k2, b0);
                a1 = ffma2(qpA[3], k3, a1);  b1 = ffma2(qpB[3], k3, b1);
                a0 = ffma2(qpA[4], k4, a0);  b0 = ffma2(qpB[4], k4, b0);
                a1 = ffma2(qpA[5], k5, a1);  b1 = ffma2(qpB[5], k5, b1);
                a0 = ffma2(qpA[6], k6, a0);  b0 = ffma2(qpB[6], k6, b0);
                a1 = ffma2(qpA[7], k7, a1);  b1 = ffma2(qpB[7], k7, b1);
                float al, ah, bl, bh, cl, ch, dl, dh;
                unpack2(a0, al, ah);
                unpack2(a1, bl, bh);
                unpack2(b0, cl, ch);
                unpack2(b1, dl, dh);
                float dA = (al + ah) + (bl + bh);
                float dB = (cl + ch) + (dl + dh);
                #pragma unroll
                for (int off = 8; off; off >>= 1) {
                    dA += __shfl_xor_sync(0xffffffffu, dA, off);
                    dB += __shfl_xor_sync(0xffffffffu, dB, off);
                }
                if (hl == 0) {
                    sc[rA * MSEG + c0 + j] = dA * 0.0625f;   // 1/sqrt(256)
                    sc[rB * MSEG + c0 + j] = dB * 0.0625f;
                }
            }
        }
        __syncthreads();

        // Softmax: warp w normalizes rows 2w, 2w+1.
        #pragma unroll
        for (int rr2 = 0; rr2 < 2; rr2++) {
            float* row = sc + (warp * 2 + rr2) * MSEG;
            float mx = -INFINITY;
            for (int j = lane; j < m; j += 32) mx = fmaxf(mx, row[j]);
            #pragma unroll
            for (int off = 16; off; off >>= 1)
                mx = fmaxf(mx, __shfl_xor_sync(0xffffffffu, mx, off));
            float sum = 0.f;
            for (int j = lane; j < m; j += 32) {
                const float v = __expf(row[j] - mx);
                row[j] = v;
                sum += v;
            }
            #pragma unroll
            for (int off = 16; off; off >>= 1)
                sum += __shfl_xor_sync(0xffffffffu, sum, off);
            const float inv = 1.f / sum;
            for (int j = lane; j < m; j += 32) row[j] *= inv;
        }
        __syncthreads();
    }

    // Segment-only attn write (matrix pre-zeroed by cudaMemsetAsync).
    for (int r = 0; r < nr; r++) {
        float* arow = attn + (size_t)(row0 + r) * N_MOL;
        const float* row = sc + r * MSEG;
        for (int c = s + tid; c < e_eff; c += 256)
            arow[c] = row[c - s];
    }

    // ---- PV: acc2[r] f32x2, lo = even-key partial, hi = odd-key partial ----
    unsigned long long acc2[TQ];
    #pragma unroll
    for (int r = 0; r < TQ; r++) acc2[r] = 0ull;

    int j = 0;
    for (; j + 3 < m; j += 4) {
        const float v0 = g_V[(size_t)(s + j + 0) * HIDDEN + tid];
        const float v1 = g_V[(size_t)(s + j + 1) * HIDDEN + tid];
        const float v2 = g_V[(size_t)(s + j + 2) * HIDDEN + tid];
        const float v3 = g_V[(size_t)(s + j + 3) * HIDDEN + tid];
        const unsigned long long vv01 = pack2(v0, v1);
        const unsigned long long vv23 = pack2(v2, v3);
        #pragma unroll
        for (int r = 0; r < TQ; r++) {
            unsigned long long p01, p23;
            lds_v2u64(p01, p23, sc_base + (uint32_t)(r * MSEG + j) * 4u);
            unsigned long long a = acc2[r];
            a = ffma2(p01, vv01, a);
            a = ffma2(p23, vv23, a);
            acc2[r] = a;
        }
    }
    for (; j < m; j++) {
        const float v0 = g_V[(size_t)(s + j) * HIDDEN + tid];
        const unsigned long long vv = pack2(v0, 0.f);
        #pragma unroll
        for (int r = 0; r < TQ; r++) {
            const unsigned long long pp = pack2(sc[r * MSEG + j], 0.f);
            acc2[r] = ffma2(pp, vv, acc2[r]);
        }
    }

    #pragma unroll
    for (int r = 0; r < TQ; r++) {
        float lo, hi;
        unpack2(acc2[r], lo, hi);
        if (r < nr) out[(size_t)(row0 + r) * HIDDEN + tid] = lo + hi;
    }
}

// ---------------------------------------------------------------------------
extern "C" void kernel_launch(void* const* d_in, const int* in_sizes, int n_in,
                              void* d_out, int out_size)
{
    const float* prot_embed = (const float*)d_in[0];
    const float* mol_embed  = (const float*)d_in[1];
    const int*   prot_batch = (const int*)d_in[2];
    const int*   mol_batch  = (const int*)d_in[3];
    const float* Wq = (const float*)d_in[4];
    const float* bq = (const float*)d_in[5];
    const float* Wk = (const float*)d_in[6];
    const float* bk = (const float*)d_in[7];
    const float* Wv = (const float*)d_in[8];
    const float* bv = (const float*)d_in[9];

    float* out  = (float*)d_out;                              // [N_PROT, HIDDEN]
    float* attn = (float*)d_out + (size_t)N_PROT * HIDDEN;    // [N_PROT, N_MOL]

    // Zero the attn matrix via a graph-capturable memset node (no allocation).
    cudaMemsetAsync(attn, 0, (size_t)N_PROT * N_MOL * sizeof(float), 0);

    bounds_kernel<<<(N_PROT + 255) / 256, 256>>>(prot_batch, mol_batch);
    tiles_kernel<<<1, 32>>>();
    proj_kernel<<<NPROJ, 256>>>(prot_embed, mol_embed, Wq, bq, Wk, bk, Wv, bv);
    attn_kernel<<<MAXTILES, 256>>>(out, attn);
}